// round 8
// baseline (speedup 1.0000x reference)
#include <cuda_runtime.h>
#include <cuda_fp16.h>
#include <cstdint>
#include <cstddef>

#define N_NODES 20000
#define MPAD    20096            // 157 * 128, padded M for transposed operand arrays
#define F_IN  256
#define F_HID 512
#define F_OUT 256
#define ELL   128

// ---------------- scratch (no allocations allowed) ----------------
__device__ float    g_inv[N_NODES];
__device__ int      g_cnt[N_NODES];
__device__ int      g_esrc[(size_t)N_NODES * ELL];
__device__ int      g_is64;
// split-transposed operands: word (k2, m) = half2(X[m][2k2], X[m][2k2+1])
__device__ uint32_t g_P1h[(size_t)(F_IN  / 2) * MPAD];
__device__ uint32_t g_P1l[(size_t)(F_IN  / 2) * MPAD];
__device__ uint32_t g_H1h[(size_t)(F_HID / 2) * MPAD];
__device__ uint32_t g_H1l[(size_t)(F_HID / 2) * MPAD];
// split weights: word (k2, n) = half2(W[2k2][n], W[2k2+1][n])
__device__ uint32_t g_W1h[(size_t)(F_IN  / 2) * F_HID];
__device__ uint32_t g_W1l[(size_t)(F_IN  / 2) * F_HID];
__device__ uint32_t g_W2h[(size_t)(F_HID / 2) * F_OUT];
__device__ uint32_t g_W2l[(size_t)(F_HID / 2) * F_OUT];
__device__ float    g_T[(size_t)N_NODES * F_OUT];      // GEMM2 out (fp32, row-major)

// ---------------- helpers ----------------
__device__ __forceinline__ int load_idx(const void* e, long long pos, int is64) {
    if (is64) return (int)((const long long*)e)[pos];
    return ((const int*)e)[pos];
}

// split two fp32 into packed half2 hi and half2 lo (x = low half)
__device__ __forceinline__ void splitf2(float x, float y, uint32_t& hi, uint32_t& lo) {
    __half hx = __float2half_rn(x), hy = __float2half_rn(y);
    __half lx = __float2half_rn(x - __half2float(hx));
    __half ly = __float2half_rn(y - __half2float(hy));
    __half2 h = __halves2half2(hx, hy);
    __half2 l = __halves2half2(lx, ly);
    hi = *reinterpret_cast<uint32_t*>(&h);
    lo = *reinterpret_cast<uint32_t*>(&l);
}

// ---------------- graph build ----------------
__global__ void k_prep(const int* __restrict__ e) {
    int i = blockIdx.x * blockDim.x + threadIdx.x;
    if (i < N_NODES) g_cnt[i] = 0;
    if (blockIdx.x == 0) {
        __shared__ int nz;
        if (threadIdx.x == 0) nz = 0;
        __syncthreads();
        for (int j = threadIdx.x; j < 1024; j += blockDim.x)
            if (e[2 * j + 1] != 0) atomicOr(&nz, 1);
        __syncthreads();
        if (threadIdx.x == 0) g_is64 = (nz == 0) ? 1 : 0;
    }
}

__global__ void k_fill(const void* __restrict__ e, int E) {
    int i = blockIdx.x * blockDim.x + threadIdx.x;
    if (i >= E) return;
    int is64 = g_is64;
    int s = load_idx(e, i, is64);
    int d = load_idx(e, (long long)E + i, is64);
    int slot = atomicAdd(&g_cnt[d], 1);
    if (slot < ELL) g_esrc[(size_t)d * ELL + slot] = s;
}

__global__ void k_inv() {
    int i = blockIdx.x * blockDim.x + threadIdx.x;
    if (i < N_NODES) g_inv[i] = rsqrtf((float)(g_cnt[i] + 1));
}

// ---------------- weight split: W[K][N] fp32 -> Wh/Wl [K/2][N] half2 words ----------------
__global__ void k_wsplit(const float* __restrict__ W, uint32_t* __restrict__ Wh,
                         uint32_t* __restrict__ Wl, int K2, int N) {
    int i = blockIdx.x * blockDim.x + threadIdx.x;
    if (i >= K2 * N) return;
    int k2 = i / N, n = i - k2 * N;
    float x = W[(size_t)(2 * k2) * N + n];
    float y = W[(size_t)(2 * k2 + 1) * N + n];
    splitf2(x, y, Wh[i], Wl[i]);
}

// ---------------- ELL gather: one warp per destination node ----------------
// out = inv[d]^2 * in[d] (+bias) + sum_j inv[src_j]*inv[d]*in[src_j]
// out_split: write split-transposed half2 arrays; else fp32 row-major.
__device__ __forceinline__ void fma4(float4& a, float nr, const float4& v) {
    a.x += nr * v.x; a.y += nr * v.y; a.z += nr * v.z; a.w += nr * v.w;
}

__global__ void __launch_bounds__(256) k_gather(const float4* __restrict__ in,
                                                float4* __restrict__ out_f32,
                                                uint32_t* __restrict__ outh,
                                                uint32_t* __restrict__ outl,
                                                const float4* __restrict__ bias,
                                                int out_split) {
    int d    = (int)((blockIdx.x * blockDim.x + threadIdx.x) >> 5);
    int lane = threadIdx.x & 31;
    if (d >= N_NODES) return;

    float iv = g_inv[d];
    float s2 = iv * iv;
    const float4* sp = in + (size_t)d * 64;
    float4 a0 = sp[lane];
    float4 a1 = sp[lane + 32];
    a0.x *= s2; a0.y *= s2; a0.z *= s2; a0.w *= s2;
    a1.x *= s2; a1.y *= s2; a1.z *= s2; a1.w *= s2;
    if (bias) {
        float4 b0 = bias[lane], b1 = bias[lane + 32];
        a0.x += b0.x; a0.y += b0.y; a0.z += b0.z; a0.w += b0.w;
        a1.x += b1.x; a1.y += b1.y; a1.z += b1.z; a1.w += b1.w;
    }

    int cnt = min(g_cnt[d], ELL);
    const int* bucket = g_esrc + (size_t)d * ELL;
    for (int j0 = 0; j0 < cnt; j0 += 32) {
        int myj = j0 + lane;
        int   sl = (myj < cnt) ? bucket[myj] : 0;
        float nl = (myj < cnt) ? g_inv[sl] * iv : 0.f;
        int c = min(32, cnt - j0);
        int t = 0;
        for (; t + 4 <= c; t += 4) {
            int   si0 = __shfl_sync(0xFFFFFFFFu, sl, t);
            int   si1 = __shfl_sync(0xFFFFFFFFu, sl, t + 1);
            int   si2 = __shfl_sync(0xFFFFFFFFu, sl, t + 2);
            int   si3 = __shfl_sync(0xFFFFFFFFu, sl, t + 3);
            float n0 = __shfl_sync(0xFFFFFFFFu, nl, t);
            float n1 = __shfl_sync(0xFFFFFFFFu, nl, t + 1);
            float n2 = __shfl_sync(0xFFFFFFFFu, nl, t + 2);
            float n3 = __shfl_sync(0xFFFFFFFFu, nl, t + 3);
            const float4* q0 = in + (size_t)si0 * 64;
            const float4* q1 = in + (size_t)si1 * 64;
            const float4* q2 = in + (size_t)si2 * 64;
            const float4* q3 = in + (size_t)si3 * 64;
            float4 u0 = q0[lane], w0 = q0[lane + 32];
            float4 u1 = q1[lane], w1 = q1[lane + 32];
            float4 u2 = q2[lane], w2 = q2[lane + 32];
            float4 u3 = q3[lane], w3 = q3[lane + 32];
            fma4(a0, n0, u0); fma4(a1, n0, w0);
            fma4(a0, n1, u1); fma4(a1, n1, w1);
            fma4(a0, n2, u2); fma4(a1, n2, w2);
            fma4(a0, n3, u3); fma4(a1, n3, w3);
        }
        for (; t < c; t++) {
            int   si = __shfl_sync(0xFFFFFFFFu, sl, t);
            float nr = __shfl_sync(0xFFFFFFFFu, nl, t);
            const float4* q = in + (size_t)si * 64;
            float4 v0 = q[lane];
            float4 v1 = q[lane + 32];
            fma4(a0, nr, v0); fma4(a1, nr, v1);
        }
    }

    if (!out_split) {
        out_f32[(size_t)d * 64 + lane]      = a0;
        out_f32[(size_t)d * 64 + lane + 32] = a1;
    } else {
        // features of a0: 4*lane..4*lane+3 -> k2 = 2*lane, 2*lane+1
        // features of a1: 128+4*lane..    -> k2 = 64+2*lane, 64+2*lane+1
        uint32_t h, l;
        int k2 = 2 * lane;
        splitf2(a0.x, a0.y, h, l); outh[(size_t)k2 * MPAD + d] = h;       outl[(size_t)k2 * MPAD + d] = l;
        splitf2(a0.z, a0.w, h, l); outh[(size_t)(k2 + 1) * MPAD + d] = h; outl[(size_t)(k2 + 1) * MPAD + d] = l;
        k2 = 64 + 2 * lane;
        splitf2(a1.x, a1.y, h, l); outh[(size_t)k2 * MPAD + d] = h;       outl[(size_t)k2 * MPAD + d] = l;
        splitf2(a1.z, a1.w, h, l); outh[(size_t)(k2 + 1) * MPAD + d] = h; outl[(size_t)(k2 + 1) * MPAD + d] = l;
    }
}

// ---------------- 3xFP16 GEMM on pre-split operands ----------------
// A (split-transposed): Ah/Al [K/2][MPAD] half2 words. B: Bh/Bl [K/2][N].
// C = act(A@B + bias); out either fp32 [M][N] or split-transposed [N/2][MPAD].

__device__ __forceinline__ void mma_f16(float* d, const uint32_t* a, const uint32_t* b) {
    asm volatile(
        "mma.sync.aligned.m16n8k16.row.col.f32.f16.f16.f32 "
        "{%0,%1,%2,%3}, {%4,%5,%6,%7}, {%8,%9}, {%0,%1,%2,%3};"
        : "+f"(d[0]), "+f"(d[1]), "+f"(d[2]), "+f"(d[3])
        : "r"(a[0]), "r"(a[1]), "r"(a[2]), "r"(a[3]), "r"(b[0]), "r"(b[1]));
}

__device__ __forceinline__ void cp16(void* smem_dst, const void* gsrc) {
    uint32_t dst = (uint32_t)__cvta_generic_to_shared(smem_dst);
    asm volatile("cp.async.cg.shared.global [%0], [%1], 16;\n" :: "r"(dst), "l"(gsrc));
}

#define BM 128
#define BN 128
#define SROW 136   // half2 words per k2-row (128 + 8 pad); 544B, 16B-aligned

__global__ void __launch_bounds__(256) gemm3xf16(const uint32_t* __restrict__ Ah,
                                                 const uint32_t* __restrict__ Al,
                                                 const uint32_t* __restrict__ Bh,
                                                 const uint32_t* __restrict__ Bl,
                                                 const float* __restrict__ bias,
                                                 float* __restrict__ Cf,
                                                 uint32_t* __restrict__ Ch,
                                                 uint32_t* __restrict__ Cl,
                                                 int M, int N, int K2, int relu, int out_split) {
    __shared__ uint32_t As_h[2][8][SROW], As_l[2][8][SROW];
    __shared__ uint32_t Bs_h[2][8][SROW], Bs_l[2][8][SROW];

    const int tid  = threadIdx.x;
    const int lane = tid & 31;
    const int warp = tid >> 5;
    const int g = lane >> 2;
    const int t = lane & 3;

    const int bm0 = blockIdx.x * BM;
    const int bn0 = blockIdx.y * BN;
    const int warp_m = warp & 3;
    const int warp_n = warp >> 2;

    float acc[2][8][4];
#pragma unroll
    for (int mt = 0; mt < 2; mt++)
#pragma unroll
        for (int nt = 0; nt < 8; nt++)
#pragma unroll
            for (int i = 0; i < 4; i++) acc[mt][nt][i] = 0.0f;

    const int lrow = tid >> 5;        // k2 row in tile (0..7)
    const int lch  = (tid & 31) * 4;  // word offset (chunk of 4 words = 16B)

    auto load_tile = [&](int buf, int k20) {
        const size_t ar = (size_t)(k20 + lrow) * MPAD + bm0 + lch;
        const size_t br = (size_t)(k20 + lrow) * N    + bn0 + lch;
        cp16(&As_h[buf][lrow][lch], Ah + ar);
        cp16(&As_l[buf][lrow][lch], Al + ar);
        cp16(&Bs_h[buf][lrow][lch], Bh + br);
        cp16(&Bs_l[buf][lrow][lch], Bl + br);
        asm volatile("cp.async.commit_group;\n");
    };

    load_tile(0, 0);
    const int nk = K2 / 8;   // 8 k2-rows (=16 k) per iter

    for (int ki = 0; ki < nk; ki++) {
        asm volatile("cp.async.wait_group 0;\n");
        __syncthreads();
        const int cur = ki & 1;
        if (ki + 1 < nk) load_tile((ki + 1) & 1, (ki + 1) * 8);

        uint32_t ah[2][4], al[2][4];
#pragma unroll
        for (int mt = 0; mt < 2; mt++) {
            int r = warp_m * 32 + mt * 16 + g;
            ah[mt][0] = As_h[cur][t][r];         al[mt][0] = As_l[cur][t][r];
            ah[mt][1] = As_h[cur][t][r + 8];     al[mt][1] = As_l[cur][t][r + 8];
            ah[mt][2] = As_h[cur][t + 4][r];     al[mt][2] = As_l[cur][t + 4][r];
            ah[mt][3] = As_h[cur][t + 4][r + 8]; al[mt][3] = As_l[cur][t + 4][r + 8];
        }
#pragma unroll
        for (int nt = 0; nt < 8; nt++) {
            int c = warp_n * 64 + nt * 8 + g;
            uint32_t bh[2], bl[2];
            bh[0] = Bs_h[cur][t][c];     bh[1] = Bs_h[cur][t + 4][c];
            bl[0] = Bs_l[cur][t][c];     bl[1] = Bs_l[cur][t + 4][c];
#pragma unroll
            for (int mt = 0; mt < 2; mt++) {
                mma_f16(acc[mt][nt], ah[mt], bh);
                mma_f16(acc[mt][nt], al[mt], bh);
                mma_f16(acc[mt][nt], ah[mt], bl);
            }
        }
    }

    // ---- epilogue ----
#pragma unroll
    for (int mt = 0; mt < 2; mt++) {
        int r0 = bm0 + warp_m * 32 + mt * 16 + g;
#pragma unroll
        for (int nt = 0; nt < 8; nt++) {
            int cc = bn0 + warp_n * 64 + nt * 8 + 2 * t;
            float2 v0, v1;
            v0.x = acc[mt][nt][0]; v0.y = acc[mt][nt][1];
            v1.x = acc[mt][nt][2]; v1.y = acc[mt][nt][3];
            if (bias) {
                float bx = bias[cc], by = bias[cc + 1];
                v0.x += bx; v0.y += by;
                v1.x += bx; v1.y += by;
            }
            if (relu) {
                v0.x = fmaxf(v0.x, 0.f); v0.y = fmaxf(v0.y, 0.f);
                v1.x = fmaxf(v1.x, 0.f); v1.y = fmaxf(v1.y, 0.f);
            }
            if (!out_split) {
                if (r0 < M)     *(float2*)(Cf + (size_t)r0 * N + cc) = v0;
                if (r0 + 8 < M) *(float2*)(Cf + (size_t)(r0 + 8) * N + cc) = v1;
            } else {
                // (v0.x, v0.y) is exactly the k-pair (cc, cc+1) for row r0
                size_t w = (size_t)(cc >> 1) * MPAD;
                uint32_t h, l;
                if (r0 < M)     { splitf2(v0.x, v0.y, h, l); Ch[w + r0] = h;     Cl[w + r0] = l; }
                if (r0 + 8 < M) { splitf2(v1.x, v1.y, h, l); Ch[w + r0 + 8] = h; Cl[w + r0 + 8] = l; }
            }
        }
    }
}

// ---------------- launch ----------------
extern "C" void kernel_launch(void* const* d_in, const int* in_sizes, int n_in,
                              void* d_out, int out_size) {
    const float* x  = (const float*)d_in[0];
    const void*  ei = d_in[1];
    const float* W1 = (const float*)d_in[2];
    const float* b1 = (const float*)d_in[3];
    const float* W2 = (const float*)d_in[4];
    const float* b2 = (const float*)d_in[5];
    float* out = (float*)d_out;

    int E = in_sizes[1] / 2;

    uint32_t *P1h, *P1l, *H1h, *H1l, *W1h, *W1l, *W2h, *W2l;
    float *T;
    cudaGetSymbolAddress((void**)&P1h, g_P1h); cudaGetSymbolAddress((void**)&P1l, g_P1l);
    cudaGetSymbolAddress((void**)&H1h, g_H1h); cudaGetSymbolAddress((void**)&H1l, g_H1l);
    cudaGetSymbolAddress((void**)&W1h, g_W1h); cudaGetSymbolAddress((void**)&W1l, g_W1l);
    cudaGetSymbolAddress((void**)&W2h, g_W2h); cudaGetSymbolAddress((void**)&W2l, g_W2l);
    cudaGetSymbolAddress((void**)&T,   g_T);

    const int TPB = 256;
    int nodeBlocks = (N_NODES + TPB - 1) / TPB;
    int edgeBlocks = (E + TPB - 1) / TPB;
    int gatherBlocks = (N_NODES * 32 + TPB - 1) / TPB;

    // graph build + weight split
    k_prep<<<nodeBlocks, TPB>>>((const int*)ei);
    k_fill<<<edgeBlocks, TPB>>>(ei, E);
    k_inv<<<nodeBlocks, TPB>>>();
    k_wsplit<<<(F_IN / 2 * F_HID + TPB - 1) / TPB, TPB>>>(W1, W1h, W1l, F_IN / 2, F_HID);
    k_wsplit<<<(F_HID / 2 * F_OUT + TPB - 1) / TPB, TPB>>>(W2, W2h, W2l, F_HID / 2, F_OUT);

    // Layer 1: gather (writes P1 split-transposed), GEMM1 (writes H1 split-transposed)
    k_gather<<<gatherBlocks, TPB>>>((const float4*)x, nullptr, P1h, P1l, nullptr, 1);
    {
        dim3 grid((N_NODES + BM - 1) / BM, F_HID / BN);
        gemm3xf16<<<grid, TPB>>>(P1h, P1l, W1h, W1l, b1, nullptr, H1h, H1l,
                                 N_NODES, F_HID, F_IN / 2, 1, 1);
    }
    // Layer 2: GEMM2 (fp32 out), gather (+b2)
    {
        dim3 grid((N_NODES + BM - 1) / BM, F_OUT / BN);
        gemm3xf16<<<grid, TPB>>>(H1h, H1l, W2h, W2l, nullptr, T, nullptr, nullptr,
                                 N_NODES, F_OUT, F_HID / 2, 0, 0);
    }
    k_gather<<<gatherBlocks, TPB>>>((const float4*)T, (float4*)out, nullptr, nullptr,
                                    (const float4*)b2, 0);
}

// round 10
// speedup vs baseline: 1.0291x; 1.0291x over previous
#include <cuda_runtime.h>
#include <cuda_fp16.h>
#include <cstdint>
#include <cstddef>

#define N_NODES 20000
#define MPAD    20096
#define F_IN  256
#define F_HID 512
#define F_OUT 256
#define ELL   128

// ---------------- scratch (no allocations allowed) ----------------
__device__ int      g_cnt[N_NODES];
__device__ int      g_esrc[(size_t)N_NODES * ELL];
__device__ int      g_is64;
// row-major fp16 split operands: word (m, k2) = half2(X[m][2k2], X[m][2k2+1])
__device__ uint32_t g_P1h[(size_t)MPAD * (F_IN  / 2)];
__device__ uint32_t g_P1l[(size_t)MPAD * (F_IN  / 2)];
__device__ uint32_t g_H1h[(size_t)MPAD * (F_HID / 2)];
__device__ uint32_t g_H1l[(size_t)MPAD * (F_HID / 2)];
// split weights, k-pair packed: word (k2, n) = half2(W[2k2][n], W[2k2+1][n])
__device__ uint32_t g_W1h[(size_t)(F_IN  / 2) * F_HID];
__device__ uint32_t g_W1l[(size_t)(F_IN  / 2) * F_HID];
__device__ uint32_t g_W2h[(size_t)(F_HID / 2) * F_OUT];
__device__ uint32_t g_W2l[(size_t)(F_HID / 2) * F_OUT];
__device__ float    g_T[(size_t)N_NODES * F_OUT];

// ---------------- helpers ----------------
__device__ __forceinline__ int load_idx(const void* e, long long pos, int is64) {
    if (is64) return (int)((const long long*)e)[pos];
    return ((const int*)e)[pos];
}

__device__ __forceinline__ void splitf2(float x, float y, uint32_t& hi, uint32_t& lo) {
    __half hx = __float2half_rn(x), hy = __float2half_rn(y);
    __half lx = __float2half_rn(x - __half2float(hx));
    __half ly = __float2half_rn(y - __half2float(hy));
    __half2 h = __halves2half2(hx, hy);
    __half2 l = __halves2half2(lx, ly);
    hi = *reinterpret_cast<uint32_t*>(&h);
    lo = *reinterpret_cast<uint32_t*>(&l);
}

// ---------------- fused prep: cnt zero + dtype detect + both weight splits ----
// grid: 256 blocks x 256 threads = 65536 threads
__global__ void k_prep_all(const int* __restrict__ e,
                           const float* __restrict__ W1,
                           const float* __restrict__ W2) {
    int i = blockIdx.x * blockDim.x + threadIdx.x;
    if (i < N_NODES) g_cnt[i] = 0;
    // W1 split: [K2=128][N=512] k-pair-packed words
    {
        int k2 = i >> 9, n = i & 511;   // i < 65536
        float x = W1[(size_t)(2 * k2) * F_HID + n];
        float y = W1[(size_t)(2 * k2 + 1) * F_HID + n];
        splitf2(x, y, g_W1h[i], g_W1l[i]);
    }
    // W2 split: [K2=256][N=256]
    {
        int k2 = i >> 8, n = i & 255;
        float x = W2[(size_t)(2 * k2) * F_OUT + n];
        float y = W2[(size_t)(2 * k2 + 1) * F_OUT + n];
        splitf2(x, y, g_W2h[i], g_W2l[i]);
    }
    if (blockIdx.x == 0) {
        __shared__ int nz;
        if (threadIdx.x == 0) nz = 0;
        __syncthreads();
        for (int j = threadIdx.x; j < 1024; j += blockDim.x)
            if (e[2 * j + 1] != 0) atomicOr(&nz, 1);
        __syncthreads();
        if (threadIdx.x == 0) g_is64 = (nz == 0) ? 1 : 0;
    }
}

__global__ void k_fill(const void* __restrict__ e, int E) {
    int i = blockIdx.x * blockDim.x + threadIdx.x;
    if (i >= E) return;
    int is64 = g_is64;
    int s = load_idx(e, i, is64);
    int d = load_idx(e, (long long)E + i, is64);
    int slot = atomicAdd(&g_cnt[d], 1);
    if (slot < ELL) g_esrc[(size_t)d * ELL + slot] = s;
}

// ---------------- ELL gather (inv computed on the fly from g_cnt) ----------------
__device__ __forceinline__ void fma4(float4& a, float nr, const float4& v) {
    a.x += nr * v.x; a.y += nr * v.y; a.z += nr * v.z; a.w += nr * v.w;
}

__global__ void __launch_bounds__(256) k_gather(const float4* __restrict__ in,
                                                float4* __restrict__ out_f32,
                                                uint32_t* __restrict__ outh,
                                                uint32_t* __restrict__ outl,
                                                const float4* __restrict__ bias,
                                                int out_split) {
    int d    = (int)((blockIdx.x * blockDim.x + threadIdx.x) >> 5);
    int lane = threadIdx.x & 31;
    if (d >= N_NODES) return;

    int cnt = min(g_cnt[d], ELL);
    float iv = rsqrtf((float)(cnt + 1 > 1 ? g_cnt[d] + 1 : g_cnt[d] + 1));
    iv = rsqrtf((float)(g_cnt[d] + 1));
    float s2 = iv * iv;
    const float4* sp = in + (size_t)d * 64;
    float4 a0 = sp[lane];
    float4 a1 = sp[lane + 32];
    a0.x *= s2; a0.y *= s2; a0.z *= s2; a0.w *= s2;
    a1.x *= s2; a1.y *= s2; a1.z *= s2; a1.w *= s2;
    if (bias) {
        float4 b0 = bias[lane], b1 = bias[lane + 32];
        a0.x += b0.x; a0.y += b0.y; a0.z += b0.z; a0.w += b0.w;
        a1.x += b1.x; a1.y += b1.y; a1.z += b1.z; a1.w += b1.w;
    }

    const int* bucket = g_esrc + (size_t)d * ELL;
    for (int j0 = 0; j0 < cnt; j0 += 32) {
        int myj = j0 + lane;
        int   sl = (myj < cnt) ? bucket[myj] : 0;
        float nl = (myj < cnt) ? rsqrtf((float)(g_cnt[sl] + 1)) * iv : 0.f;
        int c = min(32, cnt - j0);
        int t = 0;
        for (; t + 4 <= c; t += 4) {
            int   si0 = __shfl_sync(0xFFFFFFFFu, sl, t);
            int   si1 = __shfl_sync(0xFFFFFFFFu, sl, t + 1);
            int   si2 = __shfl_sync(0xFFFFFFFFu, sl, t + 2);
            int   si3 = __shfl_sync(0xFFFFFFFFu, sl, t + 3);
            float n0 = __shfl_sync(0xFFFFFFFFu, nl, t);
            float n1 = __shfl_sync(0xFFFFFFFFu, nl, t + 1);
            float n2 = __shfl_sync(0xFFFFFFFFu, nl, t + 2);
            float n3 = __shfl_sync(0xFFFFFFFFu, nl, t + 3);
            const float4* q0 = in + (size_t)si0 * 64;
            const float4* q1 = in + (size_t)si1 * 64;
            const float4* q2 = in + (size_t)si2 * 64;
            const float4* q3 = in + (size_t)si3 * 64;
            float4 u0 = q0[lane], w0 = q0[lane + 32];
            float4 u1 = q1[lane], w1 = q1[lane + 32];
            float4 u2 = q2[lane], w2 = q2[lane + 32];
            float4 u3 = q3[lane], w3 = q3[lane + 32];
            fma4(a0, n0, u0); fma4(a1, n0, w0);
            fma4(a0, n1, u1); fma4(a1, n1, w1);
            fma4(a0, n2, u2); fma4(a1, n2, w2);
            fma4(a0, n3, u3); fma4(a1, n3, w3);
        }
        for (; t < c; t++) {
            int   si = __shfl_sync(0xFFFFFFFFu, sl, t);
            float nr = __shfl_sync(0xFFFFFFFFu, nl, t);
            const float4* q = in + (size_t)si * 64;
            float4 v0 = q[lane];
            float4 v1 = q[lane + 32];
            fma4(a0, nr, v0); fma4(a1, nr, v1);
        }
    }

    if (!out_split) {
        out_f32[(size_t)d * 64 + lane]      = a0;
        out_f32[(size_t)d * 64 + lane + 32] = a1;
    } else {
        // A operand layout for GEMM: [K/2][MPAD] half2 words (k2-major)
        uint32_t h, l;
        int k2 = 2 * lane;
        splitf2(a0.x, a0.y, h, l); outh[(size_t)k2 * MPAD + d] = h;       outl[(size_t)k2 * MPAD + d] = l;
        splitf2(a0.z, a0.w, h, l); outh[(size_t)(k2 + 1) * MPAD + d] = h; outl[(size_t)(k2 + 1) * MPAD + d] = l;
        k2 = 64 + 2 * lane;
        splitf2(a1.x, a1.y, h, l); outh[(size_t)k2 * MPAD + d] = h;       outl[(size_t)k2 * MPAD + d] = l;
        splitf2(a1.z, a1.w, h, l); outh[(size_t)(k2 + 1) * MPAD + d] = h; outl[(size_t)(k2 + 1) * MPAD + d] = l;
    }
}

// ---------------- 3xFP16 GEMM on pre-split operands (mma.sync m16n8k16) ----------
// A: Ah/Al [K/2][MPAD] half2 words. B: Bh/Bl [K/2][N] half2 words.
// C = act(A@B + bias); out fp32 [M][N] or split-transposed A-layout [N/2][MPAD].

__device__ __forceinline__ void mma_f16(float* d, const uint32_t* a, const uint32_t* b) {
    asm volatile(
        "mma.sync.aligned.m16n8k16.row.col.f32.f16.f16.f32 "
        "{%0,%1,%2,%3}, {%4,%5,%6,%7}, {%8,%9}, {%0,%1,%2,%3};"
        : "+f"(d[0]), "+f"(d[1]), "+f"(d[2]), "+f"(d[3])
        : "r"(a[0]), "r"(a[1]), "r"(a[2]), "r"(a[3]), "r"(b[0]), "r"(b[1]));
}

__device__ __forceinline__ void cp16(void* sd, const void* g) {
    uint32_t d;
    asm("{ .reg .u64 t; cvta.to.shared.u64 t, %1; cvt.u32.u64 %0, t; }" : "=r"(d) : "l"(sd));
    asm volatile("cp.async.cg.shared.global [%0], [%1], 16;\n" :: "r"(d), "l"(g));
}

#define BM 128
#define BN 128
#define SROW 136

__global__ void __launch_bounds__(256) gemm3xf16(const uint32_t* __restrict__ Ah,
                                                 const uint32_t* __restrict__ Al,
                                                 const uint32_t* __restrict__ Bh,
                                                 const uint32_t* __restrict__ Bl,
                                                 const float* __restrict__ bias,
                                                 float* __restrict__ Cf,
                                                 uint32_t* __restrict__ Ch,
                                                 uint32_t* __restrict__ Cl,
                                                 int M, int N, int K2, int relu, int out_split) {
    __shared__ uint32_t As_h[2][8][SROW], As_l[2][8][SROW];
    __shared__ uint32_t Bs_h[2][8][SROW], Bs_l[2][8][SROW];

    const int tid  = threadIdx.x;
    const int lane = tid & 31;
    const int warp = tid >> 5;
    const int g = lane >> 2;
    const int t = lane & 3;

    const int bm0 = blockIdx.x * BM;
    const int bn0 = blockIdx.y * BN;
    const int warp_m = warp & 3;
    const int warp_n = warp >> 2;

    float acc[2][8][4];
#pragma unroll
    for (int mt = 0; mt < 2; mt++)
#pragma unroll
        for (int nt = 0; nt < 8; nt++)
#pragma unroll
            for (int i = 0; i < 4; i++) acc[mt][nt][i] = 0.0f;

    const int lrow = tid >> 5;        // k2 row in tile (0..7)
    const int lch  = (tid & 31) * 4;  // word chunk (16B)

    auto load_tile = [&](int buf, int k20) {
        const size_t ar = (size_t)(k20 + lrow) * MPAD + bm0 + lch;
        const size_t br = (size_t)(k20 + lrow) * N    + bn0 + lch;
        cp16(&As_h[buf][lrow][lch], Ah + ar);
        cp16(&As_l[buf][lrow][lch], Al + ar);
        cp16(&Bs_h[buf][lrow][lch], Bh + br);
        cp16(&Bs_l[buf][lrow][lch], Bl + br);
        asm volatile("cp.async.commit_group;\n");
    };

    load_tile(0, 0);
    const int nk = K2 / 8;

    for (int ki = 0; ki < nk; ki++) {
        asm volatile("cp.async.wait_group 0;\n");
        __syncthreads();
        const int cur = ki & 1;
        if (ki + 1 < nk) load_tile((ki + 1) & 1, (ki + 1) * 8);

        uint32_t ah[2][4], al[2][4];
#pragma unroll
        for (int mt = 0; mt < 2; mt++) {
            int r = warp_m * 32 + mt * 16 + g;
            ah[mt][0] = As_h[cur][t][r];         al[mt][0] = As_l[cur][t][r];
            ah[mt][1] = As_h[cur][t][r + 8];     al[mt][1] = As_l[cur][t][r + 8];
            ah[mt][2] = As_h[cur][t + 4][r];     al[mt][2] = As_l[cur][t + 4][r];
            ah[mt][3] = As_h[cur][t + 4][r + 8]; al[mt][3] = As_l[cur][t + 4][r + 8];
        }
#pragma unroll
        for (int nt = 0; nt < 8; nt++) {
            int c = warp_n * 64 + nt * 8 + g;
            uint32_t bh[2], bl[2];
            bh[0] = Bs_h[cur][t][c];     bh[1] = Bs_h[cur][t + 4][c];
            bl[0] = Bs_l[cur][t][c];     bl[1] = Bs_l[cur][t + 4][c];
#pragma unroll
            for (int mt = 0; mt < 2; mt++) {
                mma_f16(acc[mt][nt], ah[mt], bh);
                mma_f16(acc[mt][nt], al[mt], bh);
                mma_f16(acc[mt][nt], ah[mt], bl);
            }
        }
    }

    // ---- epilogue ----
#pragma unroll
    for (int mt = 0; mt < 2; mt++) {
        int r0 = bm0 + warp_m * 32 + mt * 16 + g;
#pragma unroll
        for (int nt = 0; nt < 8; nt++) {
            int cc = bn0 + warp_n * 64 + nt * 8 + 2 * t;
            float2 v0, v1;
            v0.x = acc[mt][nt][0]; v0.y = acc[mt][nt][1];
            v1.x = acc[mt][nt][2]; v1.y = acc[mt][nt][3];
            if (bias) {
                float bx = bias[cc], by = bias[cc + 1];
                v0.x += bx; v0.y += by;
                v1.x += bx; v1.y += by;
            }
            if (relu) {
                v0.x = fmaxf(v0.x, 0.f); v0.y = fmaxf(v0.y, 0.f);
                v1.x = fmaxf(v1.x, 0.f); v1.y = fmaxf(v1.y, 0.f);
            }
            if (!out_split) {
                if (r0 < M)     *(float2*)(Cf + (size_t)r0 * N + cc) = v0;
                if (r0 + 8 < M) *(float2*)(Cf + (size_t)(r0 + 8) * N + cc) = v1;
            } else {
                size_t w = (size_t)(cc >> 1) * MPAD;
                uint32_t h, l;
                if (r0 < M)     { splitf2(v0.x, v0.y, h, l); Ch[w + r0] = h;     Cl[w + r0] = l; }
                if (r0 + 8 < M) { splitf2(v1.x, v1.y, h, l); Ch[w + r0 + 8] = h; Cl[w + r0 + 8] = l; }
            }
        }
    }
}

// ---------------- launch ----------------
extern "C" void kernel_launch(void* const* d_in, const int* in_sizes, int n_in,
                              void* d_out, int out_size) {
    const float* x  = (const float*)d_in[0];
    const void*  ei = d_in[1];
    const float* W1 = (const float*)d_in[2];
    const float* b1 = (const float*)d_in[3];
    const float* W2 = (const float*)d_in[4];
    const float* b2 = (const float*)d_in[5];
    float* out = (float*)d_out;

    int E = in_sizes[1] / 2;

    uint32_t *P1h, *P1l, *H1h, *H1l, *W1h, *W1l, *W2h, *W2l;
    float *T;
    cudaGetSymbolAddress((void**)&P1h, g_P1h); cudaGetSymbolAddress((void**)&P1l, g_P1l);
    cudaGetSymbolAddress((void**)&H1h, g_H1h); cudaGetSymbolAddress((void**)&H1l, g_H1l);
    cudaGetSymbolAddress((void**)&W1h, g_W1h); cudaGetSymbolAddress((void**)&W1l, g_W1l);
    cudaGetSymbolAddress((void**)&W2h, g_W2h); cudaGetSymbolAddress((void**)&W2l, g_W2l);
    cudaGetSymbolAddress((void**)&T,   g_T);

    const int TPB = 256;
    int edgeBlocks = (E + TPB - 1) / TPB;
    int gatherBlocks = (N_NODES * 32 + TPB - 1) / TPB;
    int mBlocks = (N_NODES + BM - 1) / BM;

    // launch 0: fused prep (cnt zero + detect + weight splits)
    k_prep_all<<<256, TPB>>>((const int*)ei, W1, W2);
    // launch 1: ELL fill
    k_fill<<<edgeBlocks, TPB>>>(ei, E);
    // launch 2: gather1 -> P1 split (A layout)
    k_gather<<<gatherBlocks, TPB>>>((const float4*)x, nullptr, P1h, P1l, nullptr, 1);
    // launch 3: GEMM1 (ncu -s 5 / +2 offset lands here)
    {
        dim3 grid(mBlocks, F_HID / BN);
        gemm3xf16<<<grid, TPB>>>(P1h, P1l, W1h, W1l, b1, nullptr, H1h, H1l,
                                 N_NODES, F_HID, F_IN / 2, 1, 1);
    }
    // launch 4: GEMM2
    {
        dim3 grid(mBlocks, F_OUT / BN);
        gemm3xf16<<<grid, TPB>>>(H1h, H1l, W2h, W2l, nullptr, T, nullptr, nullptr,
                                 N_NODES, F_OUT, F_HID / 2, 0, 0);
    }
    // launch 5: gather2 (+b2) -> out
    k_gather<<<gatherBlocks, TPB>>>((const float4*)T, (float4*)out, nullptr, nullptr,
                                    (const float4*)b2, 0);
}